// round 14
// baseline (speedup 1.0000x reference)
#include <cuda_runtime.h>
#include <cuda_fp16.h>
#include <math.h>
#include <stdint.h>

#define N_NODES 49998
#define E_EDGES 800000
#define DIN 128
#define NH0 8
#define DOUT 32
#define F0 (NH0 * DOUT)   // 256
#define F1 32
#define NE_PAIRS (N_NODES / 3)  // 16666
#define FULLMASK 0xffffffffu
#define SCAN_BLOCKS ((N_NODES + 1023) / 1024)   // 49

// ---------------- scratch (device globals: no runtime alloc allowed) ----------------
__device__ __half g_f0h[N_NODES * F0];   // layer0 projected features (fp16)
__device__ __half g_hh[N_NODES * F0];    // elu(gat0 out) (fp16)
__device__ float g_el0[N_NODES * NH0];
__device__ float g_er0[N_NODES * NH0];
__device__ __half g_f1h[N_NODES * F1];   // layer1 projected features (fp16)
__device__ float g_el1[N_NODES];
__device__ float g_er1[N_NODES];
__device__ float g_h1[N_NODES * F1];
__device__ int   g_cnt[N_NODES];
__device__ int   g_rowptr[N_NODES + 1];
__device__ int   g_cur[N_NODES];
__device__ int   g_esrc[E_EDGES];
__device__ int   g_bsum[64];
__device__ int   g_boff[64];

// ---------------- CSR build ----------------
// 8 edges per thread, int4 loads (MLP=8)
__global__ void k_count(const int* __restrict__ dst) {
    int t = blockIdx.x * blockDim.x + threadIdx.x;
    if (t * 8 >= E_EDGES) return;
    const int4* d4 = (const int4*)dst;
    int4 a = d4[t * 2], b = d4[t * 2 + 1];
    atomicAdd(&g_cnt[a.x], 1); atomicAdd(&g_cnt[a.y], 1);
    atomicAdd(&g_cnt[a.z], 1); atomicAdd(&g_cnt[a.w], 1);
    atomicAdd(&g_cnt[b.x], 1); atomicAdd(&g_cnt[b.y], 1);
    atomicAdd(&g_cnt[b.z], 1); atomicAdd(&g_cnt[b.w], 1);
}

// block-level exclusive scan (coalesced), writes local scan + block sums
__global__ void k_scan1() {
    int i = blockIdx.x * 1024 + threadIdx.x;
    int v = (i < N_NODES) ? g_cnt[i] : 0;
    int lane = threadIdx.x & 31, wid = threadIdx.x >> 5;
    int x = v;
#pragma unroll
    for (int o = 1; o < 32; o <<= 1) {
        int y = __shfl_up_sync(FULLMASK, x, o);
        if (lane >= o) x += y;
    }
    __shared__ int wsum[32];
    if (lane == 31) wsum[wid] = x;
    __syncthreads();
    if (wid == 0) {
        int y = wsum[lane];
#pragma unroll
        for (int o = 1; o < 32; o <<= 1) {
            int z = __shfl_up_sync(FULLMASK, y, o);
            if (lane >= o) y += z;
        }
        wsum[lane] = y;
    }
    __syncthreads();
    int excl = x - v + (wid > 0 ? wsum[wid - 1] : 0);
    if (i < N_NODES) g_rowptr[i] = excl;       // block-local exclusive
    if (threadIdx.x == 0) g_bsum[blockIdx.x] = wsum[31];
}

// scan the 49 block sums (64 threads)
__global__ void k_scan2() {
    const int NB = SCAN_BLOCKS;
    int tid = threadIdx.x;
    int v = (tid < NB) ? g_bsum[tid] : 0;
    int lane = tid & 31, w = tid >> 5;
    int x = v;
#pragma unroll
    for (int o = 1; o < 32; o <<= 1) {
        int y = __shfl_up_sync(FULLMASK, x, o);
        if (lane >= o) x += y;
    }
    __shared__ int ws[2];
    if (lane == 31) ws[w] = x;
    __syncthreads();
    if (w == 1) x += ws[0];
    if (tid < NB) g_boff[tid] = x - v;
    if (tid == NB - 1) g_rowptr[N_NODES] = x;
}

// add block offsets, emit cursor copy
__global__ void k_scan3() {
    int i = blockIdx.x * 1024 + threadIdx.x;
    if (i < N_NODES) {
        int r = g_rowptr[i] + g_boff[blockIdx.x];
        g_rowptr[i] = r;
        g_cur[i] = r;
    }
}

__global__ void k_fill(const int* __restrict__ src, const int* __restrict__ dst) {
    int t = blockIdx.x * blockDim.x + threadIdx.x;
    if (t * 8 >= E_EDGES) return;
    const int4* d4 = (const int4*)dst;
    const int4* s4 = (const int4*)src;
    int4 da = d4[t * 2], db = d4[t * 2 + 1];
    int4 sa = s4[t * 2], sb = s4[t * 2 + 1];
    int p;
    p = atomicAdd(&g_cur[da.x], 1); g_esrc[p] = sa.x;
    p = atomicAdd(&g_cur[da.y], 1); g_esrc[p] = sa.y;
    p = atomicAdd(&g_cur[da.z], 1); g_esrc[p] = sa.z;
    p = atomicAdd(&g_cur[da.w], 1); g_esrc[p] = sa.w;
    p = atomicAdd(&g_cur[db.x], 1); g_esrc[p] = sb.x;
    p = atomicAdd(&g_cur[db.y], 1); g_esrc[p] = sb.y;
    p = atomicAdd(&g_cur[db.z], 1); g_esrc[p] = sb.z;
    p = atomicAdd(&g_cur[db.w], 1); g_esrc[p] = sb.w;
}

// ---------------- tf32 tensor-core GEMM + fused attention scores ----------------
__device__ __forceinline__ uint32_t f2tf(float f) {
    uint32_t r;
    asm("cvt.rna.tf32.f32 %0, %1;" : "=r"(r) : "f"(f));
    return r;
}

__device__ __forceinline__ void mma_tf32(float* d, const uint32_t* a, const uint32_t* b) {
    asm volatile(
        "mma.sync.aligned.m16n8k8.row.col.f32.tf32.tf32.f32 "
        "{%0,%1,%2,%3},{%4,%5,%6,%7},{%8,%9},{%0,%1,%2,%3};\n"
        : "+f"(d[0]), "+f"(d[1]), "+f"(d[2]), "+f"(d[3])
        : "r"(a[0]), "r"(a[1]), "r"(a[2]), "r"(a[3]), "r"(b[0]), "r"(b[1]));
}

// C(MxNc) = A(MxK) @ B(KxNc), tf32 inputs, fp32 accumulate.
// HALF_IN: A is __half. HALF_OUT: C stored as __half. SCORES needs WN==32.
template <int BM, int BN, int BK, int WM, int WN, int NH,
          bool SCORES, bool HALF_IN, bool HALF_OUT>
__global__ void k_gemm_tf32(const void* __restrict__ Av, const float* __restrict__ B,
                            void* __restrict__ Cv, int M, int Nc, int K,
                            const float* __restrict__ al, const float* __restrict__ ar,
                            float* __restrict__ el, float* __restrict__ er) {
    constexpr int WARPS_M = BM / WM;
    constexpr int WARPS_N = BN / WN;
    constexpr int THREADS = WARPS_M * WARPS_N * 32;
    constexpr int MT = WM / 16;
    constexpr int NT = WN / 8;
    constexpr int AP = BK + 4;
    constexpr int BP = BN + 8;

    __shared__ uint32_t As[BM][AP];
    __shared__ uint32_t Bs[BK][BP];

    const int tid = threadIdx.x;
    const int wid = tid >> 5, lane = tid & 31;
    const int wm = (wid / WARPS_N) * WM;
    const int wn = (wid % WARPS_N) * WN;
    const int g = lane >> 2, t = lane & 3;
    const int row0 = blockIdx.y * BM, col0 = blockIdx.x * BN;

    float acc[MT][NT][4];
#pragma unroll
    for (int mt = 0; mt < MT; mt++)
#pragma unroll
        for (int nt = 0; nt < NT; nt++)
#pragma unroll
            for (int j = 0; j < 4; j++) acc[mt][nt][j] = 0.f;

    constexpr int A_CG = BK / 4;
    constexpr int A_RPP = THREADS / A_CG;
    constexpr int NB4 = BN / 4;
    constexpr int B_RPP = THREADS / NB4;

    for (int k0 = 0; k0 < K; k0 += BK) {
#pragma unroll
        for (int i = 0; i < BM / A_RPP; i++) {
            int r = (tid / A_CG) + i * A_RPP;
            int c = (tid % A_CG) * 4;
            int gr = row0 + r;
            float vx = 0.f, vy = 0.f, vz = 0.f, vw = 0.f;
            if (HALF_IN) {
                if (gr < M) {
                    uint2 v = *(const uint2*)((const __half*)Av + (long)gr * K + k0 + c);
                    float2 x0 = __half22float2(*(__half2*)&v.x);
                    float2 x1 = __half22float2(*(__half2*)&v.y);
                    vx = x0.x; vy = x0.y; vz = x1.x; vw = x1.y;
                }
            } else {
                if (gr < M) {
                    float4 v = *(const float4*)((const float*)Av + (long)gr * K + k0 + c);
                    vx = v.x; vy = v.y; vz = v.z; vw = v.w;
                }
            }
            As[r][c + 0] = f2tf(vx);
            As[r][c + 1] = f2tf(vy);
            As[r][c + 2] = f2tf(vz);
            As[r][c + 3] = f2tf(vw);
        }
#pragma unroll
        for (int i = 0; i < BK / B_RPP; i++) {
            int r = tid / NB4 + i * B_RPP;
            int c = (tid % NB4) * 4;
            float4 v = *(const float4*)&B[(long)(k0 + r) * Nc + col0 + c];
            Bs[r][c + 0] = f2tf(v.x);
            Bs[r][c + 1] = f2tf(v.y);
            Bs[r][c + 2] = f2tf(v.z);
            Bs[r][c + 3] = f2tf(v.w);
        }
        __syncthreads();

#pragma unroll
        for (int ks = 0; ks < BK / 8; ks++) {
            const int k8 = ks * 8;
            uint32_t af[MT][4], bf[NT][2];
#pragma unroll
            for (int mt = 0; mt < MT; mt++) {
                int r = wm + mt * 16;
                af[mt][0] = As[r + g][k8 + t];
                af[mt][1] = As[r + g + 8][k8 + t];
                af[mt][2] = As[r + g][k8 + t + 4];
                af[mt][3] = As[r + g + 8][k8 + t + 4];
            }
#pragma unroll
            for (int nt = 0; nt < NT; nt++) {
                int c = wn + nt * 8 + g;
                bf[nt][0] = Bs[k8 + t][c];
                bf[nt][1] = Bs[k8 + t + 4][c];
            }
#pragma unroll
            for (int mt = 0; mt < MT; mt++)
#pragma unroll
                for (int nt = 0; nt < NT; nt++) mma_tf32(acc[mt][nt], af[mt], bf[nt]);
        }
        __syncthreads();
    }

#pragma unroll
    for (int mt = 0; mt < MT; mt++) {
#pragma unroll
        for (int nt = 0; nt < NT; nt++) {
            int mr = row0 + wm + mt * 16 + g;
            int c = col0 + wn + nt * 8 + 2 * t;
            if (HALF_OUT) {
                __half* C = (__half*)Cv;
                if (mr < M)
                    *(__half2*)&C[(long)mr * Nc + c] = __floats2half2_rn(acc[mt][nt][0], acc[mt][nt][1]);
                if (mr + 8 < M)
                    *(__half2*)&C[(long)(mr + 8) * Nc + c] = __floats2half2_rn(acc[mt][nt][2], acc[mt][nt][3]);
            } else {
                float* C = (float*)Cv;
                if (mr < M)
                    *(float2*)&C[(long)mr * Nc + c] = make_float2(acc[mt][nt][0], acc[mt][nt][1]);
                if (mr + 8 < M)
                    *(float2*)&C[(long)(mr + 8) * Nc + c] = make_float2(acc[mt][nt][2], acc[mt][nt][3]);
            }
        }
    }

    if (SCORES) {
        const int h = (col0 + wn) >> 5;
#pragma unroll
        for (int mt = 0; mt < MT; mt++) {
            float elA = 0.f, erA = 0.f;
            float elB = 0.f, erB = 0.f;
#pragma unroll
            for (int nt = 0; nt < NT; nt++) {
#pragma unroll
                for (int j = 0; j < 2; j++) {
                    int c = nt * 8 + 2 * t + j;
                    float av = al[h * 32 + c];
                    float rv = ar[h * 32 + c];
                    elA += acc[mt][nt][j] * av;
                    erA += acc[mt][nt][j] * rv;
                    elB += acc[mt][nt][2 + j] * av;
                    erB += acc[mt][nt][2 + j] * rv;
                }
            }
#pragma unroll
            for (int o = 1; o < 4; o <<= 1) {
                elA += __shfl_xor_sync(FULLMASK, elA, o);
                erA += __shfl_xor_sync(FULLMASK, erA, o);
                elB += __shfl_xor_sync(FULLMASK, elB, o);
                erB += __shfl_xor_sync(FULLMASK, erB, o);
            }
            if (t == 0) {
                int r = row0 + wm + mt * 16 + g;
                if (r < M) { el[r * NH + h] = elA; er[r * NH + h] = erA; }
                if (r + 8 < M) { el[(r + 8) * NH + h] = elB; er[(r + 8) * NH + h] = erB; }
            }
        }
    }
}

// ---------------- layer-0 aggregation: 2 warps per node, ×8 in-flight gathers ----------------
// warp half w owns heads [4w,4w+4) / dims [128w,128w+128); lane owns 4 dims.
__global__ void k_agg0(const float* __restrict__ b0) {
    __shared__ float swW[8][32 * 5];   // [warp-in-block][edge*5 + head(0..3)]

    int gt = blockIdx.x * blockDim.x + threadIdx.x;
    int gw = gt >> 5, lane = gt & 31;
    int warp = threadIdx.x >> 5;
    int n = gw >> 1, half = gw & 1;
    if (n >= N_NODES) return;
    int beg = g_rowptr[n], end = g_rowptr[n + 1];
    int deg = end - beg;
    const int hsel = lane >> 3;        // head within our 4

    float4 er4 = *(const float4*)&g_er0[n * NH0 + half * 4];
    float er[4] = {er4.x, er4.y, er4.z, er4.w};

    float acc[4] = {0.f, 0.f, 0.f, 0.f};
    float wsum = 0.f;                  // per-head total (identical across 8-lane groups)

    for (int base = 0; base < deg; base += 32) {
        int i = base + lane;
        int s = 0;                      // pad: row 0 with weight 0
        float w[4] = {0.f, 0.f, 0.f, 0.f};
        if (i < deg) {
            s = g_esrc[beg + i];
            float4 el4 = *(const float4*)&g_el0[s * NH0 + half * 4];
            float ev[4] = {el4.x, el4.y, el4.z, el4.w};
#pragma unroll
            for (int h = 0; h < 4; h++) {
                float e = ev[h] + er[h];
                e = (e > 0.f) ? e : 0.2f * e;
                w[h] = __expf(e);
            }
        }
#pragma unroll
        for (int h = 0; h < 4; h++) swW[warp][lane * 5 + h] = w[h];
        __syncwarp();

        int cnt = deg - base; if (cnt > 32) cnt = 32;
        int cnt8 = (cnt + 7) & ~7;      // padded lanes have w=0, s=0 (safe)
        for (int j = 0; j < cnt8; j += 8) {
            int ss[8]; float ww[8]; uint2 rr[8];
#pragma unroll
            for (int u = 0; u < 8; u++) {
                ss[u] = __shfl_sync(FULLMASK, s, j + u);
                ww[u] = swW[warp][(j + u) * 5 + hsel];
                wsum += ww[u];
            }
#pragma unroll
            for (int u = 0; u < 8; u++)
                rr[u] = *(const uint2*)&g_f0h[ss[u] * F0 + half * 128 + lane * 4];
#pragma unroll
            for (int u = 0; u < 8; u++) {
                float2 a0 = __half22float2(*(__half2*)&rr[u].x);
                float2 a1 = __half22float2(*(__half2*)&rr[u].y);
                acc[0] += ww[u] * a0.x; acc[1] += ww[u] * a0.y;
                acc[2] += ww[u] * a1.x; acc[3] += ww[u] * a1.y;
            }
        }
        __syncwarp();
    }

    float inv = (deg > 0) ? (1.f / wsum) : 0.f;

    float4 b4 = *(const float4*)&b0[half * 128 + lane * 4];
    float bb[4] = {b4.x, b4.y, b4.z, b4.w};
    uint2 pack;
    __half2* hp = (__half2*)&pack;
#pragma unroll
    for (int q = 0; q < 2; q++) {
        float t0 = acc[2 * q + 0] * inv + bb[2 * q + 0];
        float t1 = acc[2 * q + 1] * inv + bb[2 * q + 1];
        t0 = (t0 > 0.f) ? t0 : expm1f(t0);
        t1 = (t1 > 0.f) ? t1 : expm1f(t1);
        hp[q] = __floats2half2_rn(t0, t1);
    }
    *(uint2*)&g_hh[n * F0 + half * 128 + lane * 4] = pack;
}

// ---------------- layer-1 aggregation (×4-unrolled, fp16 gather) ----------------
__global__ void k_agg1(const float* __restrict__ b1) {
    int g = blockIdx.x * blockDim.x + threadIdx.x;
    int n = g >> 5, lane = g & 31;
    if (n >= N_NODES) return;
    int beg = g_rowptr[n], end = g_rowptr[n + 1];
    int deg = end - beg;
    float er = g_er1[n];

    float acc = 0.f, wsum = 0.f;
    for (int base = 0; base < deg; base += 32) {
        int i = base + lane;
        int s = 0;
        float w = 0.f;
        if (i < deg) {
            s = g_esrc[beg + i];
            float e = g_el1[s] + er;
            e = (e > 0.f) ? e : 0.2f * e;
            w = __expf(e);
        }
        int cnt = deg - base; if (cnt > 32) cnt = 32;
        int cnt4 = (cnt + 3) & ~3;
        for (int j = 0; j < cnt4; j += 4) {
            int s0 = __shfl_sync(FULLMASK, s, j + 0);
            int s1 = __shfl_sync(FULLMASK, s, j + 1);
            int s2 = __shfl_sync(FULLMASK, s, j + 2);
            int s3 = __shfl_sync(FULLMASK, s, j + 3);
            float w0 = __shfl_sync(FULLMASK, w, j + 0);
            float w1 = __shfl_sync(FULLMASK, w, j + 1);
            float w2 = __shfl_sync(FULLMASK, w, j + 2);
            float w3 = __shfl_sync(FULLMASK, w, j + 3);
            wsum += (w0 + w1) + (w2 + w3);
            float f0v = __half2float(g_f1h[s0 * F1 + lane]);
            float f1v = __half2float(g_f1h[s1 * F1 + lane]);
            float f2v = __half2float(g_f1h[s2 * F1 + lane]);
            float f3v = __half2float(g_f1h[s3 * F1 + lane]);
            acc += w0 * f0v + w1 * f1v + w2 * f2v + w3 * f3v;
        }
    }

    float v = (deg > 0) ? (acc / wsum) : 0.f;
    g_h1[n * F1 + lane] = v + b1[lane];
}

// ---------------- link predictor MLP: warp per pair ----------------
__global__ void k_pred(const float* __restrict__ P1, const float* __restrict__ pb1,
                       const float* __restrict__ P2, const float* __restrict__ pb2,
                       const float* __restrict__ P3, const float* __restrict__ pb3,
                       float* __restrict__ out) {
    __shared__ float sP1[1024], sP2[1024], sP3[32], sb1[32], sb2[32];
    for (int i = threadIdx.x; i < 1024; i += blockDim.x) { sP1[i] = P1[i]; sP2[i] = P2[i]; }
    if (threadIdx.x < 32) {
        sP3[threadIdx.x] = P3[threadIdx.x];
        sb1[threadIdx.x] = pb1[threadIdx.x];
        sb2[threadIdx.x] = pb2[threadIdx.x];
    }
    __syncthreads();

    int g = blockIdx.x * blockDim.x + threadIdx.x;
    int w = g >> 5, lane = g & 31;
    if (w >= 2 * NE_PAIRS) return;
    int neg = (w >= NE_PAIRS) ? 1 : 0;
    int i = w - neg * NE_PAIRS;

    float a = g_h1[i * F1 + lane];
    int dst_row = neg ? (2 * NE_PAIRS + i) : (NE_PAIRS + i);
    float z = a * g_h1[dst_row * F1 + lane];

    float y = sb1[lane];
#pragma unroll
    for (int d = 0; d < 32; d++) {
        float zd = __shfl_sync(FULLMASK, z, d);
        y += zd * sP1[d * 32 + lane];
    }
    y = fmaxf(y, 0.f);
    float y2 = sb2[lane];
#pragma unroll
    for (int d = 0; d < 32; d++) {
        float yd = __shfl_sync(FULLMASK, y, d);
        y2 += yd * sP2[d * 32 + lane];
    }
    y2 = fmaxf(y2, 0.f);
    float t = y2 * sP3[lane];
#pragma unroll
    for (int o = 16; o; o >>= 1) t += __shfl_xor_sync(FULLMASK, t, o);
    if (lane == 0) out[neg * NE_PAIRS + i] = t + pb3[0];
}

// ---------------- launch ----------------
extern "C" void kernel_launch(void* const* d_in, const int* in_sizes, int n_in,
                              void* d_out, int out_size) {
    const float* x   = (const float*)d_in[0];
    const int*   src = (const int*)d_in[1];
    const int*   dst = (const int*)d_in[2];
    const float* W0  = (const float*)d_in[4];
    const float* al0 = (const float*)d_in[5];
    const float* ar0 = (const float*)d_in[6];
    const float* b0  = (const float*)d_in[7];
    const float* W1  = (const float*)d_in[8];
    const float* al1 = (const float*)d_in[9];
    const float* ar1 = (const float*)d_in[10];
    const float* b1  = (const float*)d_in[11];
    const float* P1  = (const float*)d_in[12];
    const float* pb1 = (const float*)d_in[13];
    const float* P2  = (const float*)d_in[14];
    const float* pb2 = (const float*)d_in[15];
    const float* P3  = (const float*)d_in[16];
    const float* pb3 = (const float*)d_in[17];
    float* out = (float*)d_out;

    void *p_f0h, *p_f1h, *p_hh, *p_cnt;
    float *p_el0, *p_er0, *p_el1, *p_er1;
    cudaGetSymbolAddress(&p_f0h, g_f0h);
    cudaGetSymbolAddress(&p_f1h, g_f1h);
    cudaGetSymbolAddress(&p_hh, g_hh);
    cudaGetSymbolAddress(&p_cnt, g_cnt);
    cudaGetSymbolAddress((void**)&p_el0, g_el0);
    cudaGetSymbolAddress((void**)&p_er0, g_er0);
    cudaGetSymbolAddress((void**)&p_el1, g_el1);
    cudaGetSymbolAddress((void**)&p_er1, g_er1);

    static cudaStream_t sB = nullptr;
    static cudaEvent_t evFork = nullptr, evJoin = nullptr;
    if (sB == nullptr) {
        cudaStreamCreateWithFlags(&sB, cudaStreamNonBlocking);
        cudaEventCreateWithFlags(&evFork, cudaEventDisableTiming);
        cudaEventCreateWithFlags(&evJoin, cudaEventDisableTiming);
    }

    cudaEventRecord(evFork, 0);
    cudaStreamWaitEvent(sB, evFork, 0);

    // branch B: CSR by dst (memset + 8-edges/thread count/fill + parallel scan)
    cudaMemsetAsync(p_cnt, 0, N_NODES * sizeof(int), sB);
    k_count<<<(E_EDGES / 8 + 255) / 256, 256, 0, sB>>>(dst);
    k_scan1<<<SCAN_BLOCKS, 1024, 0, sB>>>();
    k_scan2<<<1, 64, 0, sB>>>();
    k_scan3<<<SCAN_BLOCKS, 1024, 0, sB>>>();
    k_fill<<<(E_EDGES / 8 + 255) / 256, 256, 0, sB>>>(src, dst);
    cudaEventRecord(evJoin, sB);

    // branch A: layer-0 GEMM (tf32) + fused scores, fp16 out
    k_gemm_tf32<128, 64, 32, 32, 32, NH0, true, false, true>
        <<<dim3(F0 / 64, (N_NODES + 127) / 128), 256>>>(
            x, W0, p_f0h, N_NODES, F0, DIN, al0, ar0, p_el0, p_er0);

    cudaStreamWaitEvent(0, evJoin, 0);

    // 2 warps per node
    k_agg0<<<(2 * N_NODES + 7) / 8, 256>>>(b0);

    // layer 1: tf32 GEMM, fp16 in (g_hh), fp16 out, fused scores
    k_gemm_tf32<128, 32, 32, 16, 32, 1, true, true, true>
        <<<dim3(1, (N_NODES + 127) / 128), 256>>>(
            p_hh, W1, p_f1h, N_NODES, F1, F0, al1, ar1, p_el1, p_er1);
    k_agg1<<<(N_NODES * 32 + 255) / 256, 256>>>(b1);

    // predictor
    k_pred<<<(2 * NE_PAIRS * 32 + 255) / 256, 256>>>(P1, pb1, P2, pb2, P3, pb3, out);
}

// round 15
// speedup vs baseline: 1.5061x; 1.5061x over previous
#include <cuda_runtime.h>
#include <cuda_fp16.h>
#include <math.h>
#include <stdint.h>

#define N_NODES 49998
#define E_EDGES 800000
#define DIN 128
#define NH0 8
#define DOUT 32
#define F0 (NH0 * DOUT)   // 256
#define F1 32
#define NE_PAIRS (N_NODES / 3)  // 16666
#define FULLMASK 0xffffffffu
#define SCAN_BLOCKS ((N_NODES + 1023) / 1024)   // 49

// ---------------- scratch (device globals: no runtime alloc allowed) ----------------
__device__ __half g_f0h[N_NODES * F0];   // layer0 projected features (fp16)
__device__ __half g_hh[N_NODES * F0];    // elu(gat0 out) (fp16)
__device__ float g_el0[N_NODES * NH0];
__device__ float g_er0[N_NODES * NH0];
__device__ __half g_f1h[N_NODES * F1];   // layer1 projected features (fp16)
__device__ float g_el1[N_NODES];
__device__ float g_er1[N_NODES];
__device__ float g_h1[N_NODES * F1];
__device__ int   g_cnt[N_NODES];
__device__ int   g_rowptr[N_NODES + 1];
__device__ int   g_cur[N_NODES];
__device__ int   g_esrc[E_EDGES];
__device__ int   g_bsum[64];
__device__ int   g_boff[64];

// ---------------- CSR build ----------------
// 8 edges per thread, int4 loads (MLP=8)
__global__ void k_count(const int* __restrict__ dst) {
    int t = blockIdx.x * blockDim.x + threadIdx.x;
    if (t * 8 >= E_EDGES) return;
    const int4* d4 = (const int4*)dst;
    int4 a = d4[t * 2], b = d4[t * 2 + 1];
    atomicAdd(&g_cnt[a.x], 1); atomicAdd(&g_cnt[a.y], 1);
    atomicAdd(&g_cnt[a.z], 1); atomicAdd(&g_cnt[a.w], 1);
    atomicAdd(&g_cnt[b.x], 1); atomicAdd(&g_cnt[b.y], 1);
    atomicAdd(&g_cnt[b.z], 1); atomicAdd(&g_cnt[b.w], 1);
}

// block-level exclusive scan (coalesced), writes local scan + block sums
__global__ void k_scan1() {
    int i = blockIdx.x * 1024 + threadIdx.x;
    int v = (i < N_NODES) ? g_cnt[i] : 0;
    int lane = threadIdx.x & 31, wid = threadIdx.x >> 5;
    int x = v;
#pragma unroll
    for (int o = 1; o < 32; o <<= 1) {
        int y = __shfl_up_sync(FULLMASK, x, o);
        if (lane >= o) x += y;
    }
    __shared__ int wsum[32];
    if (lane == 31) wsum[wid] = x;
    __syncthreads();
    if (wid == 0) {
        int y = wsum[lane];
#pragma unroll
        for (int o = 1; o < 32; o <<= 1) {
            int z = __shfl_up_sync(FULLMASK, y, o);
            if (lane >= o) y += z;
        }
        wsum[lane] = y;
    }
    __syncthreads();
    int excl = x - v + (wid > 0 ? wsum[wid - 1] : 0);
    if (i < N_NODES) g_rowptr[i] = excl;       // block-local exclusive
    if (threadIdx.x == 0) g_bsum[blockIdx.x] = wsum[31];
}

// scan the 49 block sums (64 threads)
__global__ void k_scan2() {
    const int NB = SCAN_BLOCKS;
    int tid = threadIdx.x;
    int v = (tid < NB) ? g_bsum[tid] : 0;
    int lane = tid & 31, w = tid >> 5;
    int x = v;
#pragma unroll
    for (int o = 1; o < 32; o <<= 1) {
        int y = __shfl_up_sync(FULLMASK, x, o);
        if (lane >= o) x += y;
    }
    __shared__ int ws[2];
    if (lane == 31) ws[w] = x;
    __syncthreads();
    if (w == 1) x += ws[0];
    if (tid < NB) g_boff[tid] = x - v;
    if (tid == NB - 1) g_rowptr[N_NODES] = x;
}

// add block offsets, emit cursor copy
__global__ void k_scan3() {
    int i = blockIdx.x * 1024 + threadIdx.x;
    if (i < N_NODES) {
        int r = g_rowptr[i] + g_boff[blockIdx.x];
        g_rowptr[i] = r;
        g_cur[i] = r;
    }
}

__global__ void k_fill(const int* __restrict__ src, const int* __restrict__ dst) {
    int t = blockIdx.x * blockDim.x + threadIdx.x;
    if (t * 8 >= E_EDGES) return;
    const int4* d4 = (const int4*)dst;
    const int4* s4 = (const int4*)src;
    int4 da = d4[t * 2], db = d4[t * 2 + 1];
    int4 sa = s4[t * 2], sb = s4[t * 2 + 1];
    int p;
    p = atomicAdd(&g_cur[da.x], 1); g_esrc[p] = sa.x;
    p = atomicAdd(&g_cur[da.y], 1); g_esrc[p] = sa.y;
    p = atomicAdd(&g_cur[da.z], 1); g_esrc[p] = sa.z;
    p = atomicAdd(&g_cur[da.w], 1); g_esrc[p] = sa.w;
    p = atomicAdd(&g_cur[db.x], 1); g_esrc[p] = sb.x;
    p = atomicAdd(&g_cur[db.y], 1); g_esrc[p] = sb.y;
    p = atomicAdd(&g_cur[db.z], 1); g_esrc[p] = sb.z;
    p = atomicAdd(&g_cur[db.w], 1); g_esrc[p] = sb.w;
}

// ---------------- tf32 tensor-core GEMM + fused attention scores ----------------
__device__ __forceinline__ uint32_t f2tf(float f) {
    uint32_t r;
    asm("cvt.rna.tf32.f32 %0, %1;" : "=r"(r) : "f"(f));
    return r;
}

__device__ __forceinline__ void mma_tf32(float* d, const uint32_t* a, const uint32_t* b) {
    asm volatile(
        "mma.sync.aligned.m16n8k8.row.col.f32.tf32.tf32.f32 "
        "{%0,%1,%2,%3},{%4,%5,%6,%7},{%8,%9},{%0,%1,%2,%3};\n"
        : "+f"(d[0]), "+f"(d[1]), "+f"(d[2]), "+f"(d[3])
        : "r"(a[0]), "r"(a[1]), "r"(a[2]), "r"(a[3]), "r"(b[0]), "r"(b[1]));
}

// C(MxNc) = A(MxK) @ B(KxNc), tf32 inputs, fp32 accumulate.
// HALF_IN: A is __half. HALF_OUT: C stored as __half. SCORES needs WN==32.
template <int BM, int BN, int BK, int WM, int WN, int NH,
          bool SCORES, bool HALF_IN, bool HALF_OUT>
__global__ void k_gemm_tf32(const void* __restrict__ Av, const float* __restrict__ B,
                            void* __restrict__ Cv, int M, int Nc, int K,
                            const float* __restrict__ al, const float* __restrict__ ar,
                            float* __restrict__ el, float* __restrict__ er) {
    constexpr int WARPS_M = BM / WM;
    constexpr int WARPS_N = BN / WN;
    constexpr int THREADS = WARPS_M * WARPS_N * 32;
    constexpr int MT = WM / 16;
    constexpr int NT = WN / 8;
    constexpr int AP = BK + 4;
    constexpr int BP = BN + 8;

    __shared__ uint32_t As[BM][AP];
    __shared__ uint32_t Bs[BK][BP];

    const int tid = threadIdx.x;
    const int wid = tid >> 5, lane = tid & 31;
    const int wm = (wid / WARPS_N) * WM;
    const int wn = (wid % WARPS_N) * WN;
    const int g = lane >> 2, t = lane & 3;
    const int row0 = blockIdx.y * BM, col0 = blockIdx.x * BN;

    float acc[MT][NT][4];
#pragma unroll
    for (int mt = 0; mt < MT; mt++)
#pragma unroll
        for (int nt = 0; nt < NT; nt++)
#pragma unroll
            for (int j = 0; j < 4; j++) acc[mt][nt][j] = 0.f;

    constexpr int A_CG = BK / 4;
    constexpr int A_RPP = THREADS / A_CG;
    constexpr int NB4 = BN / 4;
    constexpr int B_RPP = THREADS / NB4;

    for (int k0 = 0; k0 < K; k0 += BK) {
#pragma unroll
        for (int i = 0; i < BM / A_RPP; i++) {
            int r = (tid / A_CG) + i * A_RPP;
            int c = (tid % A_CG) * 4;
            int gr = row0 + r;
            float vx = 0.f, vy = 0.f, vz = 0.f, vw = 0.f;
            if (HALF_IN) {
                if (gr < M) {
                    uint2 v = *(const uint2*)((const __half*)Av + (long)gr * K + k0 + c);
                    float2 x0 = __half22float2(*(__half2*)&v.x);
                    float2 x1 = __half22float2(*(__half2*)&v.y);
                    vx = x0.x; vy = x0.y; vz = x1.x; vw = x1.y;
                }
            } else {
                if (gr < M) {
                    float4 v = *(const float4*)((const float*)Av + (long)gr * K + k0 + c);
                    vx = v.x; vy = v.y; vz = v.z; vw = v.w;
                }
            }
            As[r][c + 0] = f2tf(vx);
            As[r][c + 1] = f2tf(vy);
            As[r][c + 2] = f2tf(vz);
            As[r][c + 3] = f2tf(vw);
        }
#pragma unroll
        for (int i = 0; i < BK / B_RPP; i++) {
            int r = tid / NB4 + i * B_RPP;
            int c = (tid % NB4) * 4;
            float4 v = *(const float4*)&B[(long)(k0 + r) * Nc + col0 + c];
            Bs[r][c + 0] = f2tf(v.x);
            Bs[r][c + 1] = f2tf(v.y);
            Bs[r][c + 2] = f2tf(v.z);
            Bs[r][c + 3] = f2tf(v.w);
        }
        __syncthreads();

#pragma unroll
        for (int ks = 0; ks < BK / 8; ks++) {
            const int k8 = ks * 8;
            uint32_t af[MT][4], bf[NT][2];
#pragma unroll
            for (int mt = 0; mt < MT; mt++) {
                int r = wm + mt * 16;
                af[mt][0] = As[r + g][k8 + t];
                af[mt][1] = As[r + g + 8][k8 + t];
                af[mt][2] = As[r + g][k8 + t + 4];
                af[mt][3] = As[r + g + 8][k8 + t + 4];
            }
#pragma unroll
            for (int nt = 0; nt < NT; nt++) {
                int c = wn + nt * 8 + g;
                bf[nt][0] = Bs[k8 + t][c];
                bf[nt][1] = Bs[k8 + t + 4][c];
            }
#pragma unroll
            for (int mt = 0; mt < MT; mt++)
#pragma unroll
                for (int nt = 0; nt < NT; nt++) mma_tf32(acc[mt][nt], af[mt], bf[nt]);
        }
        __syncthreads();
    }

#pragma unroll
    for (int mt = 0; mt < MT; mt++) {
#pragma unroll
        for (int nt = 0; nt < NT; nt++) {
            int mr = row0 + wm + mt * 16 + g;
            int c = col0 + wn + nt * 8 + 2 * t;
            if (HALF_OUT) {
                __half* C = (__half*)Cv;
                if (mr < M)
                    *(__half2*)&C[(long)mr * Nc + c] = __floats2half2_rn(acc[mt][nt][0], acc[mt][nt][1]);
                if (mr + 8 < M)
                    *(__half2*)&C[(long)(mr + 8) * Nc + c] = __floats2half2_rn(acc[mt][nt][2], acc[mt][nt][3]);
            } else {
                float* C = (float*)Cv;
                if (mr < M)
                    *(float2*)&C[(long)mr * Nc + c] = make_float2(acc[mt][nt][0], acc[mt][nt][1]);
                if (mr + 8 < M)
                    *(float2*)&C[(long)(mr + 8) * Nc + c] = make_float2(acc[mt][nt][2], acc[mt][nt][3]);
            }
        }
    }

    if (SCORES) {
        const int h = (col0 + wn) >> 5;
#pragma unroll
        for (int mt = 0; mt < MT; mt++) {
            float elA = 0.f, erA = 0.f;
            float elB = 0.f, erB = 0.f;
#pragma unroll
            for (int nt = 0; nt < NT; nt++) {
#pragma unroll
                for (int j = 0; j < 2; j++) {
                    int c = nt * 8 + 2 * t + j;
                    float av = al[h * 32 + c];
                    float rv = ar[h * 32 + c];
                    elA += acc[mt][nt][j] * av;
                    erA += acc[mt][nt][j] * rv;
                    elB += acc[mt][nt][2 + j] * av;
                    erB += acc[mt][nt][2 + j] * rv;
                }
            }
#pragma unroll
            for (int o = 1; o < 4; o <<= 1) {
                elA += __shfl_xor_sync(FULLMASK, elA, o);
                erA += __shfl_xor_sync(FULLMASK, erA, o);
                elB += __shfl_xor_sync(FULLMASK, elB, o);
                erB += __shfl_xor_sync(FULLMASK, erB, o);
            }
            if (t == 0) {
                int r = row0 + wm + mt * 16 + g;
                if (r < M) { el[r * NH + h] = elA; er[r * NH + h] = erA; }
                if (r + 8 < M) { el[(r + 8) * NH + h] = elB; er[(r + 8) * NH + h] = erB; }
            }
        }
    }
}

// ---------------- layer-0 aggregation: 2 warps per node ----------------
// warp half w owns heads [4w,4w+4) / dims [128w,128w+128); lane owns 4 dims.
__global__ void k_agg0(const float* __restrict__ b0) {
    __shared__ float swW[8][32 * 5];   // [warp-in-block][edge*5 + head(0..3)]

    int gt = blockIdx.x * blockDim.x + threadIdx.x;
    int gw = gt >> 5, lane = gt & 31;
    int warp = threadIdx.x >> 5;
    int n = gw >> 1, half = gw & 1;
    if (n >= N_NODES) return;
    int beg = g_rowptr[n], end = g_rowptr[n + 1];
    int deg = end - beg;
    const int hsel = lane >> 3;        // head within our 4

    float4 er4 = *(const float4*)&g_er0[n * NH0 + half * 4];
    float er[4] = {er4.x, er4.y, er4.z, er4.w};

    float acc[4] = {0.f, 0.f, 0.f, 0.f};
    float wsum = 0.f;                  // per-head total (identical across 8-lane groups)

    for (int base = 0; base < deg; base += 32) {
        int i = base + lane;
        int s = 0;                      // pad: row 0 with weight 0
        float w[4] = {0.f, 0.f, 0.f, 0.f};
        if (i < deg) {
            s = g_esrc[beg + i];
            float4 el4 = *(const float4*)&g_el0[s * NH0 + half * 4];
            float ev[4] = {el4.x, el4.y, el4.z, el4.w};
#pragma unroll
            for (int h = 0; h < 4; h++) {
                float e = ev[h] + er[h];
                e = (e > 0.f) ? e : 0.2f * e;
                w[h] = __expf(e);
            }
        }
#pragma unroll
        for (int h = 0; h < 4; h++) swW[warp][lane * 5 + h] = w[h];
        __syncwarp();

        int cnt = deg - base; if (cnt > 32) cnt = 32;
        int cnt4 = (cnt + 3) & ~3;      // padded lanes have w=0, s=0 (safe)
        for (int j = 0; j < cnt4; j += 4) {
            int s0 = __shfl_sync(FULLMASK, s, j + 0);
            int s1 = __shfl_sync(FULLMASK, s, j + 1);
            int s2 = __shfl_sync(FULLMASK, s, j + 2);
            int s3 = __shfl_sync(FULLMASK, s, j + 3);
            float w0 = swW[warp][(j + 0) * 5 + hsel];
            float w1 = swW[warp][(j + 1) * 5 + hsel];
            float w2 = swW[warp][(j + 2) * 5 + hsel];
            float w3 = swW[warp][(j + 3) * 5 + hsel];
            wsum += (w0 + w1) + (w2 + w3);
            uint2 r0 = *(const uint2*)&g_f0h[s0 * F0 + half * 128 + lane * 4];
            uint2 r1 = *(const uint2*)&g_f0h[s1 * F0 + half * 128 + lane * 4];
            uint2 r2 = *(const uint2*)&g_f0h[s2 * F0 + half * 128 + lane * 4];
            uint2 r3 = *(const uint2*)&g_f0h[s3 * F0 + half * 128 + lane * 4];
            {
                float2 a0 = __half22float2(*(__half2*)&r0.x);
                float2 a1 = __half22float2(*(__half2*)&r0.y);
                acc[0] += w0 * a0.x; acc[1] += w0 * a0.y;
                acc[2] += w0 * a1.x; acc[3] += w0 * a1.y;
            }
            {
                float2 a0 = __half22float2(*(__half2*)&r1.x);
                float2 a1 = __half22float2(*(__half2*)&r1.y);
                acc[0] += w1 * a0.x; acc[1] += w1 * a0.y;
                acc[2] += w1 * a1.x; acc[3] += w1 * a1.y;
            }
            {
                float2 a0 = __half22float2(*(__half2*)&r2.x);
                float2 a1 = __half22float2(*(__half2*)&r2.y);
                acc[0] += w2 * a0.x; acc[1] += w2 * a0.y;
                acc[2] += w2 * a1.x; acc[3] += w2 * a1.y;
            }
            {
                float2 a0 = __half22float2(*(__half2*)&r3.x);
                float2 a1 = __half22float2(*(__half2*)&r3.y);
                acc[0] += w3 * a0.x; acc[1] += w3 * a0.y;
                acc[2] += w3 * a1.x; acc[3] += w3 * a1.y;
            }
        }
        __syncwarp();
    }

    float inv = (deg > 0) ? (1.f / wsum) : 0.f;

    float4 b4 = *(const float4*)&b0[half * 128 + lane * 4];
    float bb[4] = {b4.x, b4.y, b4.z, b4.w};
    uint2 pack;
    __half2* hp = (__half2*)&pack;
#pragma unroll
    for (int q = 0; q < 2; q++) {
        float t0 = acc[2 * q + 0] * inv + bb[2 * q + 0];
        float t1 = acc[2 * q + 1] * inv + bb[2 * q + 1];
        t0 = (t0 > 0.f) ? t0 : expm1f(t0);
        t1 = (t1 > 0.f) ? t1 : expm1f(t1);
        hp[q] = __floats2half2_rn(t0, t1);
    }
    *(uint2*)&g_hh[n * F0 + half * 128 + lane * 4] = pack;
}

// ---------------- layer-1 aggregation (×4-unrolled, fp16 gather) ----------------
__global__ void k_agg1(const float* __restrict__ b1) {
    int g = blockIdx.x * blockDim.x + threadIdx.x;
    int n = g >> 5, lane = g & 31;
    if (n >= N_NODES) return;
    int beg = g_rowptr[n], end = g_rowptr[n + 1];
    int deg = end - beg;
    float er = g_er1[n];

    float acc = 0.f, wsum = 0.f;
    for (int base = 0; base < deg; base += 32) {
        int i = base + lane;
        int s = 0;
        float w = 0.f;
        if (i < deg) {
            s = g_esrc[beg + i];
            float e = g_el1[s] + er;
            e = (e > 0.f) ? e : 0.2f * e;
            w = __expf(e);
        }
        int cnt = deg - base; if (cnt > 32) cnt = 32;
        int cnt4 = (cnt + 3) & ~3;
        for (int j = 0; j < cnt4; j += 4) {
            int s0 = __shfl_sync(FULLMASK, s, j + 0);
            int s1 = __shfl_sync(FULLMASK, s, j + 1);
            int s2 = __shfl_sync(FULLMASK, s, j + 2);
            int s3 = __shfl_sync(FULLMASK, s, j + 3);
            float w0 = __shfl_sync(FULLMASK, w, j + 0);
            float w1 = __shfl_sync(FULLMASK, w, j + 1);
            float w2 = __shfl_sync(FULLMASK, w, j + 2);
            float w3 = __shfl_sync(FULLMASK, w, j + 3);
            wsum += (w0 + w1) + (w2 + w3);
            float f0v = __half2float(g_f1h[s0 * F1 + lane]);
            float f1v = __half2float(g_f1h[s1 * F1 + lane]);
            float f2v = __half2float(g_f1h[s2 * F1 + lane]);
            float f3v = __half2float(g_f1h[s3 * F1 + lane]);
            acc += w0 * f0v + w1 * f1v + w2 * f2v + w3 * f3v;
        }
    }

    float v = (deg > 0) ? (acc / wsum) : 0.f;
    g_h1[n * F1 + lane] = v + b1[lane];
}

// ---------------- link predictor MLP: warp per pair ----------------
__global__ void k_pred(const float* __restrict__ P1, const float* __restrict__ pb1,
                       const float* __restrict__ P2, const float* __restrict__ pb2,
                       const float* __restrict__ P3, const float* __restrict__ pb3,
                       float* __restrict__ out) {
    __shared__ float sP1[1024], sP2[1024], sP3[32], sb1[32], sb2[32];
    for (int i = threadIdx.x; i < 1024; i += blockDim.x) { sP1[i] = P1[i]; sP2[i] = P2[i]; }
    if (threadIdx.x < 32) {
        sP3[threadIdx.x] = P3[threadIdx.x];
        sb1[threadIdx.x] = pb1[threadIdx.x];
        sb2[threadIdx.x] = pb2[threadIdx.x];
    }
    __syncthreads();

    int g = blockIdx.x * blockDim.x + threadIdx.x;
    int w = g >> 5, lane = g & 31;
    if (w >= 2 * NE_PAIRS) return;
    int neg = (w >= NE_PAIRS) ? 1 : 0;
    int i = w - neg * NE_PAIRS;

    float a = g_h1[i * F1 + lane];
    int dst_row = neg ? (2 * NE_PAIRS + i) : (NE_PAIRS + i);
    float z = a * g_h1[dst_row * F1 + lane];

    float y = sb1[lane];
#pragma unroll
    for (int d = 0; d < 32; d++) {
        float zd = __shfl_sync(FULLMASK, z, d);
        y += zd * sP1[d * 32 + lane];
    }
    y = fmaxf(y, 0.f);
    float y2 = sb2[lane];
#pragma unroll
    for (int d = 0; d < 32; d++) {
        float yd = __shfl_sync(FULLMASK, y, d);
        y2 += yd * sP2[d * 32 + lane];
    }
    y2 = fmaxf(y2, 0.f);
    float t = y2 * sP3[lane];
#pragma unroll
    for (int o = 16; o; o >>= 1) t += __shfl_xor_sync(FULLMASK, t, o);
    if (lane == 0) out[neg * NE_PAIRS + i] = t + pb3[0];
}

// ---------------- launch ----------------
extern "C" void kernel_launch(void* const* d_in, const int* in_sizes, int n_in,
                              void* d_out, int out_size) {
    const float* x   = (const float*)d_in[0];
    const int*   src = (const int*)d_in[1];
    const int*   dst = (const int*)d_in[2];
    const float* W0  = (const float*)d_in[4];
    const float* al0 = (const float*)d_in[5];
    const float* ar0 = (const float*)d_in[6];
    const float* b0  = (const float*)d_in[7];
    const float* W1  = (const float*)d_in[8];
    const float* al1 = (const float*)d_in[9];
    const float* ar1 = (const float*)d_in[10];
    const float* b1  = (const float*)d_in[11];
    const float* P1  = (const float*)d_in[12];
    const float* pb1 = (const float*)d_in[13];
    const float* P2  = (const float*)d_in[14];
    const float* pb2 = (const float*)d_in[15];
    const float* P3  = (const float*)d_in[16];
    const float* pb3 = (const float*)d_in[17];
    float* out = (float*)d_out;

    void *p_f0h, *p_f1h, *p_hh, *p_cnt;
    float *p_el0, *p_er0, *p_el1, *p_er1;
    cudaGetSymbolAddress(&p_f0h, g_f0h);
    cudaGetSymbolAddress(&p_f1h, g_f1h);
    cudaGetSymbolAddress(&p_hh, g_hh);
    cudaGetSymbolAddress(&p_cnt, g_cnt);
    cudaGetSymbolAddress((void**)&p_el0, g_el0);
    cudaGetSymbolAddress((void**)&p_er0, g_er0);
    cudaGetSymbolAddress((void**)&p_el1, g_el1);
    cudaGetSymbolAddress((void**)&p_er1, g_er1);

    static cudaStream_t sB = nullptr;
    static cudaEvent_t evFork = nullptr, evJoin = nullptr;
    if (sB == nullptr) {
        cudaStreamCreateWithFlags(&sB, cudaStreamNonBlocking);
        cudaEventCreateWithFlags(&evFork, cudaEventDisableTiming);
        cudaEventCreateWithFlags(&evJoin, cudaEventDisableTiming);
    }

    cudaEventRecord(evFork, 0);
    cudaStreamWaitEvent(sB, evFork, 0);

    // branch B: CSR by dst (memset + 8-edges/thread count/fill + parallel scan)
    cudaMemsetAsync(p_cnt, 0, N_NODES * sizeof(int), sB);
    k_count<<<(E_EDGES / 8 + 255) / 256, 256, 0, sB>>>(dst);
    k_scan1<<<SCAN_BLOCKS, 1024, 0, sB>>>();
    k_scan2<<<1, 64, 0, sB>>>();
    k_scan3<<<SCAN_BLOCKS, 1024, 0, sB>>>();
    k_fill<<<(E_EDGES / 8 + 255) / 256, 256, 0, sB>>>(src, dst);
    cudaEventRecord(evJoin, sB);

    // branch A: layer-0 GEMM (tf32) + fused scores, fp16 out
    k_gemm_tf32<128, 64, 32, 32, 32, NH0, true, false, true>
        <<<dim3(F0 / 64, (N_NODES + 127) / 128), 256>>>(
            x, W0, p_f0h, N_NODES, F0, DIN, al0, ar0, p_el0, p_er0);

    cudaStreamWaitEvent(0, evJoin, 0);

    // 2 warps per node
    k_agg0<<<(2 * N_NODES + 7) / 8, 256>>>(b0);

    // layer 1: tf32 GEMM, fp16 in (g_hh), fp16 out, fused scores
    k_gemm_tf32<128, 32, 32, 16, 32, 1, true, true, true>
        <<<dim3(1, (N_NODES + 127) / 128), 256>>>(
            p_hh, W1, p_f1h, N_NODES, F1, F0, al1, ar1, p_el1, p_er1);
    k_agg1<<<(N_NODES * 32 + 255) / 256, 256>>>(b1);

    // predictor
    k_pred<<<(2 * NE_PAIRS * 32 + 255) / 256, 256>>>(P1, pb1, P2, pb2, P3, pb3, out);
}

// round 16
// speedup vs baseline: 1.5153x; 1.0061x over previous
#include <cuda_runtime.h>
#include <cuda_fp16.h>
#include <math.h>
#include <stdint.h>

#define N_NODES 49998
#define E_EDGES 800000
#define DIN 128
#define NH0 8
#define DOUT 32
#define F0 (NH0 * DOUT)   // 256
#define F1 32
#define NE_PAIRS (N_NODES / 3)  // 16666
#define FULLMASK 0xffffffffu
#define SCAN_BLOCKS ((N_NODES + 1023) / 1024)   // 49
#define CHUNK0 25000                             // node split for agg0/GEMM1 pipeline

// ---------------- scratch (device globals: no runtime alloc allowed) ----------------
__device__ __half g_f0h[N_NODES * F0];   // layer0 projected features (fp16)
__device__ __half g_hh[N_NODES * F0];    // elu(gat0 out) (fp16)
__device__ float g_el0[N_NODES * NH0];
__device__ float g_er0[N_NODES * NH0];
__device__ __half g_f1h[N_NODES * F1];   // layer1 projected features (fp16)
__device__ float g_el1[N_NODES];
__device__ float g_er1[N_NODES];
__device__ float g_h1[N_NODES * F1];
__device__ int   g_cnt[N_NODES];
__device__ int   g_rowptr[N_NODES + 1];
__device__ int   g_cur[N_NODES];
__device__ int   g_esrc[E_EDGES];
__device__ int   g_bsum[64];
__device__ int   g_boff[64];

// ---------------- CSR build ----------------
// 8 edges per thread, int4 loads (MLP=8)
__global__ void k_count(const int* __restrict__ dst) {
    int t = blockIdx.x * blockDim.x + threadIdx.x;
    if (t * 8 >= E_EDGES) return;
    const int4* d4 = (const int4*)dst;
    int4 a = d4[t * 2], b = d4[t * 2 + 1];
    atomicAdd(&g_cnt[a.x], 1); atomicAdd(&g_cnt[a.y], 1);
    atomicAdd(&g_cnt[a.z], 1); atomicAdd(&g_cnt[a.w], 1);
    atomicAdd(&g_cnt[b.x], 1); atomicAdd(&g_cnt[b.y], 1);
    atomicAdd(&g_cnt[b.z], 1); atomicAdd(&g_cnt[b.w], 1);
}

// block-level exclusive scan (coalesced), writes local scan + block sums
__global__ void k_scan1() {
    int i = blockIdx.x * 1024 + threadIdx.x;
    int v = (i < N_NODES) ? g_cnt[i] : 0;
    int lane = threadIdx.x & 31, wid = threadIdx.x >> 5;
    int x = v;
#pragma unroll
    for (int o = 1; o < 32; o <<= 1) {
        int y = __shfl_up_sync(FULLMASK, x, o);
        if (lane >= o) x += y;
    }
    __shared__ int wsum[32];
    if (lane == 31) wsum[wid] = x;
    __syncthreads();
    if (wid == 0) {
        int y = wsum[lane];
#pragma unroll
        for (int o = 1; o < 32; o <<= 1) {
            int z = __shfl_up_sync(FULLMASK, y, o);
            if (lane >= o) y += z;
        }
        wsum[lane] = y;
    }
    __syncthreads();
    int excl = x - v + (wid > 0 ? wsum[wid - 1] : 0);
    if (i < N_NODES) g_rowptr[i] = excl;       // block-local exclusive
    if (threadIdx.x == 0) g_bsum[blockIdx.x] = wsum[31];
}

// scan the 49 block sums (64 threads)
__global__ void k_scan2() {
    const int NB = SCAN_BLOCKS;
    int tid = threadIdx.x;
    int v = (tid < NB) ? g_bsum[tid] : 0;
    int lane = tid & 31, w = tid >> 5;
    int x = v;
#pragma unroll
    for (int o = 1; o < 32; o <<= 1) {
        int y = __shfl_up_sync(FULLMASK, x, o);
        if (lane >= o) x += y;
    }
    __shared__ int ws[2];
    if (lane == 31) ws[w] = x;
    __syncthreads();
    if (w == 1) x += ws[0];
    if (tid < NB) g_boff[tid] = x - v;
    if (tid == NB - 1) g_rowptr[N_NODES] = x;
}

// add block offsets, emit cursor copy
__global__ void k_scan3() {
    int i = blockIdx.x * 1024 + threadIdx.x;
    if (i < N_NODES) {
        int r = g_rowptr[i] + g_boff[blockIdx.x];
        g_rowptr[i] = r;
        g_cur[i] = r;
    }
}

__global__ void k_fill(const int* __restrict__ src, const int* __restrict__ dst) {
    int t = blockIdx.x * blockDim.x + threadIdx.x;
    if (t * 8 >= E_EDGES) return;
    const int4* d4 = (const int4*)dst;
    const int4* s4 = (const int4*)src;
    int4 da = d4[t * 2], db = d4[t * 2 + 1];
    int4 sa = s4[t * 2], sb = s4[t * 2 + 1];
    int p;
    p = atomicAdd(&g_cur[da.x], 1); g_esrc[p] = sa.x;
    p = atomicAdd(&g_cur[da.y], 1); g_esrc[p] = sa.y;
    p = atomicAdd(&g_cur[da.z], 1); g_esrc[p] = sa.z;
    p = atomicAdd(&g_cur[da.w], 1); g_esrc[p] = sa.w;
    p = atomicAdd(&g_cur[db.x], 1); g_esrc[p] = sb.x;
    p = atomicAdd(&g_cur[db.y], 1); g_esrc[p] = sb.y;
    p = atomicAdd(&g_cur[db.z], 1); g_esrc[p] = sb.z;
    p = atomicAdd(&g_cur[db.w], 1); g_esrc[p] = sb.w;
}

// ---------------- tf32 tensor-core GEMM + fused attention scores ----------------
__device__ __forceinline__ uint32_t f2tf(float f) {
    uint32_t r;
    asm("cvt.rna.tf32.f32 %0, %1;" : "=r"(r) : "f"(f));
    return r;
}

__device__ __forceinline__ void mma_tf32(float* d, const uint32_t* a, const uint32_t* b) {
    asm volatile(
        "mma.sync.aligned.m16n8k8.row.col.f32.tf32.tf32.f32 "
        "{%0,%1,%2,%3},{%4,%5,%6,%7},{%8,%9},{%0,%1,%2,%3};\n"
        : "+f"(d[0]), "+f"(d[1]), "+f"(d[2]), "+f"(d[3])
        : "r"(a[0]), "r"(a[1]), "r"(a[2]), "r"(a[3]), "r"(b[0]), "r"(b[1]));
}

// C(MxNc) = A(MxK) @ B(KxNc), tf32 inputs, fp32 accumulate.
// HALF_IN: A is __half. HALF_OUT: C stored as __half. SCORES needs WN==32.
template <int BM, int BN, int BK, int WM, int WN, int NH,
          bool SCORES, bool HALF_IN, bool HALF_OUT>
__global__ void k_gemm_tf32(const void* __restrict__ Av, const float* __restrict__ B,
                            void* __restrict__ Cv, int M, int Nc, int K,
                            const float* __restrict__ al, const float* __restrict__ ar,
                            float* __restrict__ el, float* __restrict__ er) {
    constexpr int WARPS_M = BM / WM;
    constexpr int WARPS_N = BN / WN;
    constexpr int THREADS = WARPS_M * WARPS_N * 32;
    constexpr int MT = WM / 16;
    constexpr int NT = WN / 8;
    constexpr int AP = BK + 4;
    constexpr int BP = BN + 8;

    __shared__ uint32_t As[BM][AP];
    __shared__ uint32_t Bs[BK][BP];

    const int tid = threadIdx.x;
    const int wid = tid >> 5, lane = tid & 31;
    const int wm = (wid / WARPS_N) * WM;
    const int wn = (wid % WARPS_N) * WN;
    const int g = lane >> 2, t = lane & 3;
    const int row0 = blockIdx.y * BM, col0 = blockIdx.x * BN;

    float acc[MT][NT][4];
#pragma unroll
    for (int mt = 0; mt < MT; mt++)
#pragma unroll
        for (int nt = 0; nt < NT; nt++)
#pragma unroll
            for (int j = 0; j < 4; j++) acc[mt][nt][j] = 0.f;

    constexpr int A_CG = BK / 4;
    constexpr int A_RPP = THREADS / A_CG;
    constexpr int NB4 = BN / 4;
    constexpr int B_RPP = THREADS / NB4;

    for (int k0 = 0; k0 < K; k0 += BK) {
#pragma unroll
        for (int i = 0; i < BM / A_RPP; i++) {
            int r = (tid / A_CG) + i * A_RPP;
            int c = (tid % A_CG) * 4;
            int gr = row0 + r;
            float vx = 0.f, vy = 0.f, vz = 0.f, vw = 0.f;
            if (HALF_IN) {
                if (gr < M) {
                    uint2 v = *(const uint2*)((const __half*)Av + (long)gr * K + k0 + c);
                    float2 x0 = __half22float2(*(__half2*)&v.x);
                    float2 x1 = __half22float2(*(__half2*)&v.y);
                    vx = x0.x; vy = x0.y; vz = x1.x; vw = x1.y;
                }
            } else {
                if (gr < M) {
                    float4 v = *(const float4*)((const float*)Av + (long)gr * K + k0 + c);
                    vx = v.x; vy = v.y; vz = v.z; vw = v.w;
                }
            }
            As[r][c + 0] = f2tf(vx);
            As[r][c + 1] = f2tf(vy);
            As[r][c + 2] = f2tf(vz);
            As[r][c + 3] = f2tf(vw);
        }
#pragma unroll
        for (int i = 0; i < BK / B_RPP; i++) {
            int r = tid / NB4 + i * B_RPP;
            int c = (tid % NB4) * 4;
            float4 v = *(const float4*)&B[(long)(k0 + r) * Nc + col0 + c];
            Bs[r][c + 0] = f2tf(v.x);
            Bs[r][c + 1] = f2tf(v.y);
            Bs[r][c + 2] = f2tf(v.z);
            Bs[r][c + 3] = f2tf(v.w);
        }
        __syncthreads();

#pragma unroll
        for (int ks = 0; ks < BK / 8; ks++) {
            const int k8 = ks * 8;
            uint32_t af[MT][4], bf[NT][2];
#pragma unroll
            for (int mt = 0; mt < MT; mt++) {
                int r = wm + mt * 16;
                af[mt][0] = As[r + g][k8 + t];
                af[mt][1] = As[r + g + 8][k8 + t];
                af[mt][2] = As[r + g][k8 + t + 4];
                af[mt][3] = As[r + g + 8][k8 + t + 4];
            }
#pragma unroll
            for (int nt = 0; nt < NT; nt++) {
                int c = wn + nt * 8 + g;
                bf[nt][0] = Bs[k8 + t][c];
                bf[nt][1] = Bs[k8 + t + 4][c];
            }
#pragma unroll
            for (int mt = 0; mt < MT; mt++)
#pragma unroll
                for (int nt = 0; nt < NT; nt++) mma_tf32(acc[mt][nt], af[mt], bf[nt]);
        }
        __syncthreads();
    }

#pragma unroll
    for (int mt = 0; mt < MT; mt++) {
#pragma unroll
        for (int nt = 0; nt < NT; nt++) {
            int mr = row0 + wm + mt * 16 + g;
            int c = col0 + wn + nt * 8 + 2 * t;
            if (HALF_OUT) {
                __half* C = (__half*)Cv;
                if (mr < M)
                    *(__half2*)&C[(long)mr * Nc + c] = __floats2half2_rn(acc[mt][nt][0], acc[mt][nt][1]);
                if (mr + 8 < M)
                    *(__half2*)&C[(long)(mr + 8) * Nc + c] = __floats2half2_rn(acc[mt][nt][2], acc[mt][nt][3]);
            } else {
                float* C = (float*)Cv;
                if (mr < M)
                    *(float2*)&C[(long)mr * Nc + c] = make_float2(acc[mt][nt][0], acc[mt][nt][1]);
                if (mr + 8 < M)
                    *(float2*)&C[(long)(mr + 8) * Nc + c] = make_float2(acc[mt][nt][2], acc[mt][nt][3]);
            }
        }
    }

    if (SCORES) {
        const int h = (col0 + wn) >> 5;
#pragma unroll
        for (int mt = 0; mt < MT; mt++) {
            float elA = 0.f, erA = 0.f;
            float elB = 0.f, erB = 0.f;
#pragma unroll
            for (int nt = 0; nt < NT; nt++) {
#pragma unroll
                for (int j = 0; j < 2; j++) {
                    int c = nt * 8 + 2 * t + j;
                    float av = al[h * 32 + c];
                    float rv = ar[h * 32 + c];
                    elA += acc[mt][nt][j] * av;
                    erA += acc[mt][nt][j] * rv;
                    elB += acc[mt][nt][2 + j] * av;
                    erB += acc[mt][nt][2 + j] * rv;
                }
            }
#pragma unroll
            for (int o = 1; o < 4; o <<= 1) {
                elA += __shfl_xor_sync(FULLMASK, elA, o);
                erA += __shfl_xor_sync(FULLMASK, erA, o);
                elB += __shfl_xor_sync(FULLMASK, elB, o);
                erB += __shfl_xor_sync(FULLMASK, erB, o);
            }
            if (t == 0) {
                int r = row0 + wm + mt * 16 + g;
                if (r < M) { el[r * NH + h] = elA; er[r * NH + h] = erA; }
                if (r + 8 < M) { el[(r + 8) * NH + h] = elB; er[(r + 8) * NH + h] = erB; }
            }
        }
    }
}

// ---------------- layer-0 aggregation: 2 warps per node, node-range chunk ----------------
// warp half w owns heads [4w,4w+4) / dims [128w,128w+128); lane owns 4 dims.
__global__ void k_agg0(const float* __restrict__ b0, int node_base, int node_count) {
    __shared__ float swW[8][32 * 5];   // [warp-in-block][edge*5 + head(0..3)]

    int gt = blockIdx.x * blockDim.x + threadIdx.x;
    int gw = gt >> 5, lane = gt & 31;
    int warp = threadIdx.x >> 5;
    int nl = gw >> 1, half = gw & 1;
    if (nl >= node_count) return;
    int n = node_base + nl;
    int beg = g_rowptr[n], end = g_rowptr[n + 1];
    int deg = end - beg;
    const int hsel = lane >> 3;        // head within our 4

    float4 er4 = *(const float4*)&g_er0[n * NH0 + half * 4];
    float er[4] = {er4.x, er4.y, er4.z, er4.w};

    float acc[4] = {0.f, 0.f, 0.f, 0.f};
    float wsum = 0.f;                  // per-head total (identical across 8-lane groups)

    for (int base = 0; base < deg; base += 32) {
        int i = base + lane;
        int s = 0;                      // pad: row 0 with weight 0
        float w[4] = {0.f, 0.f, 0.f, 0.f};
        if (i < deg) {
            s = g_esrc[beg + i];
            float4 el4 = *(const float4*)&g_el0[s * NH0 + half * 4];
            float ev[4] = {el4.x, el4.y, el4.z, el4.w};
#pragma unroll
            for (int h = 0; h < 4; h++) {
                float e = ev[h] + er[h];
                e = (e > 0.f) ? e : 0.2f * e;
                w[h] = __expf(e);
            }
        }
#pragma unroll
        for (int h = 0; h < 4; h++) swW[warp][lane * 5 + h] = w[h];
        __syncwarp();

        int cnt = deg - base; if (cnt > 32) cnt = 32;
        int cnt4 = (cnt + 3) & ~3;      // padded lanes have w=0, s=0 (safe)
        for (int j = 0; j < cnt4; j += 4) {
            int s0 = __shfl_sync(FULLMASK, s, j + 0);
            int s1 = __shfl_sync(FULLMASK, s, j + 1);
            int s2 = __shfl_sync(FULLMASK, s, j + 2);
            int s3 = __shfl_sync(FULLMASK, s, j + 3);
            float w0 = swW[warp][(j + 0) * 5 + hsel];
            float w1 = swW[warp][(j + 1) * 5 + hsel];
            float w2 = swW[warp][(j + 2) * 5 + hsel];
            float w3 = swW[warp][(j + 3) * 5 + hsel];
            wsum += (w0 + w1) + (w2 + w3);
            uint2 r0 = *(const uint2*)&g_f0h[s0 * F0 + half * 128 + lane * 4];
            uint2 r1 = *(const uint2*)&g_f0h[s1 * F0 + half * 128 + lane * 4];
            uint2 r2 = *(const uint2*)&g_f0h[s2 * F0 + half * 128 + lane * 4];
            uint2 r3 = *(const uint2*)&g_f0h[s3 * F0 + half * 128 + lane * 4];
            {
                float2 a0 = __half22float2(*(__half2*)&r0.x);
                float2 a1 = __half22float2(*(__half2*)&r0.y);
                acc[0] += w0 * a0.x; acc[1] += w0 * a0.y;
                acc[2] += w0 * a1.x; acc[3] += w0 * a1.y;
            }
            {
                float2 a0 = __half22float2(*(__half2*)&r1.x);
                float2 a1 = __half22float2(*(__half2*)&r1.y);
                acc[0] += w1 * a0.x; acc[1] += w1 * a0.y;
                acc[2] += w1 * a1.x; acc[3] += w1 * a1.y;
            }
            {
                float2 a0 = __half22float2(*(__half2*)&r2.x);
                float2 a1 = __half22float2(*(__half2*)&r2.y);
                acc[0] += w2 * a0.x; acc[1] += w2 * a0.y;
                acc[2] += w2 * a1.x; acc[3] += w2 * a1.y;
            }
            {
                float2 a0 = __half22float2(*(__half2*)&r3.x);
                float2 a1 = __half22float2(*(__half2*)&r3.y);
                acc[0] += w3 * a0.x; acc[1] += w3 * a0.y;
                acc[2] += w3 * a1.x; acc[3] += w3 * a1.y;
            }
        }
        __syncwarp();
    }

    float inv = (deg > 0) ? (1.f / wsum) : 0.f;

    float4 b4 = *(const float4*)&b0[half * 128 + lane * 4];
    float bb[4] = {b4.x, b4.y, b4.z, b4.w};
    uint2 pack;
    __half2* hp = (__half2*)&pack;
#pragma unroll
    for (int q = 0; q < 2; q++) {
        float t0 = acc[2 * q + 0] * inv + bb[2 * q + 0];
        float t1 = acc[2 * q + 1] * inv + bb[2 * q + 1];
        t0 = (t0 > 0.f) ? t0 : expm1f(t0);
        t1 = (t1 > 0.f) ? t1 : expm1f(t1);
        hp[q] = __floats2half2_rn(t0, t1);
    }
    *(uint2*)&g_hh[n * F0 + half * 128 + lane * 4] = pack;
}

// ---------------- layer-1 aggregation (×4-unrolled, fp16 gather) ----------------
__global__ void k_agg1(const float* __restrict__ b1) {
    int g = blockIdx.x * blockDim.x + threadIdx.x;
    int n = g >> 5, lane = g & 31;
    if (n >= N_NODES) return;
    int beg = g_rowptr[n], end = g_rowptr[n + 1];
    int deg = end - beg;
    float er = g_er1[n];

    float acc = 0.f, wsum = 0.f;
    for (int base = 0; base < deg; base += 32) {
        int i = base + lane;
        int s = 0;
        float w = 0.f;
        if (i < deg) {
            s = g_esrc[beg + i];
            float e = g_el1[s] + er;
            e = (e > 0.f) ? e : 0.2f * e;
            w = __expf(e);
        }
        int cnt = deg - base; if (cnt > 32) cnt = 32;
        int cnt4 = (cnt + 3) & ~3;
        for (int j = 0; j < cnt4; j += 4) {
            int s0 = __shfl_sync(FULLMASK, s, j + 0);
            int s1 = __shfl_sync(FULLMASK, s, j + 1);
            int s2 = __shfl_sync(FULLMASK, s, j + 2);
            int s3 = __shfl_sync(FULLMASK, s, j + 3);
            float w0 = __shfl_sync(FULLMASK, w, j + 0);
            float w1 = __shfl_sync(FULLMASK, w, j + 1);
            float w2 = __shfl_sync(FULLMASK, w, j + 2);
            float w3 = __shfl_sync(FULLMASK, w, j + 3);
            wsum += (w0 + w1) + (w2 + w3);
            float f0v = __half2float(g_f1h[s0 * F1 + lane]);
            float f1v = __half2float(g_f1h[s1 * F1 + lane]);
            float f2v = __half2float(g_f1h[s2 * F1 + lane]);
            float f3v = __half2float(g_f1h[s3 * F1 + lane]);
            acc += w0 * f0v + w1 * f1v + w2 * f2v + w3 * f3v;
        }
    }

    float v = (deg > 0) ? (acc / wsum) : 0.f;
    g_h1[n * F1 + lane] = v + b1[lane];
}

// ---------------- link predictor MLP: warp per pair ----------------
__global__ void k_pred(const float* __restrict__ P1, const float* __restrict__ pb1,
                       const float* __restrict__ P2, const float* __restrict__ pb2,
                       const float* __restrict__ P3, const float* __restrict__ pb3,
                       float* __restrict__ out) {
    __shared__ float sP1[1024], sP2[1024], sP3[32], sb1[32], sb2[32];
    for (int i = threadIdx.x; i < 1024; i += blockDim.x) { sP1[i] = P1[i]; sP2[i] = P2[i]; }
    if (threadIdx.x < 32) {
        sP3[threadIdx.x] = P3[threadIdx.x];
        sb1[threadIdx.x] = pb1[threadIdx.x];
        sb2[threadIdx.x] = pb2[threadIdx.x];
    }
    __syncthreads();

    int g = blockIdx.x * blockDim.x + threadIdx.x;
    int w = g >> 5, lane = g & 31;
    if (w >= 2 * NE_PAIRS) return;
    int neg = (w >= NE_PAIRS) ? 1 : 0;
    int i = w - neg * NE_PAIRS;

    float a = g_h1[i * F1 + lane];
    int dst_row = neg ? (2 * NE_PAIRS + i) : (NE_PAIRS + i);
    float z = a * g_h1[dst_row * F1 + lane];

    float y = sb1[lane];
#pragma unroll
    for (int d = 0; d < 32; d++) {
        float zd = __shfl_sync(FULLMASK, z, d);
        y += zd * sP1[d * 32 + lane];
    }
    y = fmaxf(y, 0.f);
    float y2 = sb2[lane];
#pragma unroll
    for (int d = 0; d < 32; d++) {
        float yd = __shfl_sync(FULLMASK, y, d);
        y2 += yd * sP2[d * 32 + lane];
    }
    y2 = fmaxf(y2, 0.f);
    float t = y2 * sP3[lane];
#pragma unroll
    for (int o = 16; o; o >>= 1) t += __shfl_xor_sync(FULLMASK, t, o);
    if (lane == 0) out[neg * NE_PAIRS + i] = t + pb3[0];
}

// ---------------- launch ----------------
extern "C" void kernel_launch(void* const* d_in, const int* in_sizes, int n_in,
                              void* d_out, int out_size) {
    const float* x   = (const float*)d_in[0];
    const int*   src = (const int*)d_in[1];
    const int*   dst = (const int*)d_in[2];
    const float* W0  = (const float*)d_in[4];
    const float* al0 = (const float*)d_in[5];
    const float* ar0 = (const float*)d_in[6];
    const float* b0  = (const float*)d_in[7];
    const float* W1  = (const float*)d_in[8];
    const float* al1 = (const float*)d_in[9];
    const float* ar1 = (const float*)d_in[10];
    const float* b1  = (const float*)d_in[11];
    const float* P1  = (const float*)d_in[12];
    const float* pb1 = (const float*)d_in[13];
    const float* P2  = (const float*)d_in[14];
    const float* pb2 = (const float*)d_in[15];
    const float* P3  = (const float*)d_in[16];
    const float* pb3 = (const float*)d_in[17];
    float* out = (float*)d_out;

    void *p_f0h, *p_f1h, *p_hh, *p_cnt;
    float *p_el0, *p_er0, *p_el1, *p_er1;
    cudaGetSymbolAddress(&p_f0h, g_f0h);
    cudaGetSymbolAddress(&p_f1h, g_f1h);
    cudaGetSymbolAddress(&p_hh, g_hh);
    cudaGetSymbolAddress(&p_cnt, g_cnt);
    cudaGetSymbolAddress((void**)&p_el0, g_el0);
    cudaGetSymbolAddress((void**)&p_er0, g_er0);
    cudaGetSymbolAddress((void**)&p_el1, g_el1);
    cudaGetSymbolAddress((void**)&p_er1, g_er1);

    static cudaStream_t sB = nullptr;
    static cudaEvent_t evFork = nullptr, evJoin = nullptr, evG0 = nullptr, evB2 = nullptr;
    if (sB == nullptr) {
        cudaStreamCreateWithFlags(&sB, cudaStreamNonBlocking);
        cudaEventCreateWithFlags(&evFork, cudaEventDisableTiming);
        cudaEventCreateWithFlags(&evJoin, cudaEventDisableTiming);
        cudaEventCreateWithFlags(&evG0, cudaEventDisableTiming);
        cudaEventCreateWithFlags(&evB2, cudaEventDisableTiming);
    }

    const int CNT0 = CHUNK0;
    const int CNT1 = N_NODES - CHUNK0;

    cudaEventRecord(evFork, 0);
    cudaStreamWaitEvent(sB, evFork, 0);

    // branch B: CSR by dst (memset + 8-edges/thread count/fill + parallel scan)
    cudaMemsetAsync(p_cnt, 0, N_NODES * sizeof(int), sB);
    k_count<<<(E_EDGES / 8 + 255) / 256, 256, 0, sB>>>(dst);
    k_scan1<<<SCAN_BLOCKS, 1024, 0, sB>>>();
    k_scan2<<<1, 64, 0, sB>>>();
    k_scan3<<<SCAN_BLOCKS, 1024, 0, sB>>>();
    k_fill<<<(E_EDGES / 8 + 255) / 256, 256, 0, sB>>>(src, dst);
    cudaEventRecord(evJoin, sB);

    // branch A: layer-0 GEMM (tf32) + fused scores, fp16 out
    k_gemm_tf32<128, 64, 32, 32, 32, NH0, true, false, true>
        <<<dim3(F0 / 64, (N_NODES + 127) / 128), 256>>>(
            x, W0, p_f0h, N_NODES, F0, DIN, al0, ar0, p_el0, p_er0);
    cudaEventRecord(evG0, 0);

    // pipeline: chunk 0 on stream A, chunk 1 on stream B (each: agg0 -> GEMM1 rows)
    cudaStreamWaitEvent(0, evJoin, 0);       // A needs CSR
    cudaStreamWaitEvent(sB, evG0, 0);        // B needs GEMM0 (f0h, el0/er0)

    // chunk 0 (stream A)
    k_agg0<<<(2 * CNT0 + 7) / 8, 256>>>(b0, 0, CNT0);
    k_gemm_tf32<128, 32, 32, 16, 32, 1, true, true, true>
        <<<dim3(1, (CNT0 + 127) / 128), 256>>>(
            p_hh, W1, p_f1h, CNT0, F1, F0, al1, ar1, p_el1, p_er1);

    // chunk 1 (stream B)
    k_agg0<<<(2 * CNT1 + 7) / 8, 256, 0, sB>>>(b0, CNT0, CNT1);
    k_gemm_tf32<128, 32, 32, 16, 32, 1, true, true, true>
        <<<dim3(1, (CNT1 + 127) / 128), 256, 0, sB>>>(
            (const __half*)p_hh + (long)CNT0 * F0, W1,
            (__half*)p_f1h + (long)CNT0 * F1, CNT1, F1, F0,
            al1, ar1, p_el1 + CNT0, p_er1 + CNT0);
    cudaEventRecord(evB2, sB);
    cudaStreamWaitEvent(0, evB2, 0);

    // tail (stream A): agg1 needs all f1h/el1/er1
    k_agg1<<<(N_NODES * 32 + 255) / 256, 256>>>(b1);
    k_pred<<<(2 * NE_PAIRS * 32 + 255) / 256, 256>>>(P1, pb1, P2, pb2, P3, pb3, out);
}